// round 14
// baseline (speedup 1.0000x reference)
#include <cuda_runtime.h>
#include <cuda_bf16.h>
#include <math.h>
#include <stdint.h>

#define Bb 4
#define Tt 2048
#define Ccn 2048
#define Hh 16
#define Dd 128
#define Mrows (Bb*Tt)   // 8192

// ---------------- scratch (device globals) ----------------
__device__ float g_invfreq[Dd/2];

__device__ __align__(256) __nv_bfloat16 g_xhi[Mrows*Ccn];
__device__ __align__(256) __nv_bfloat16 g_xlo[Mrows*Ccn];
__device__ __align__(256) __nv_bfloat16 g_qh[Mrows*Ccn];
__device__ __align__(256) __nv_bfloat16 g_ql[Mrows*Ccn];
__device__ __align__(256) __nv_bfloat16 g_kh[Mrows*Ccn];
__device__ __align__(256) __nv_bfloat16 g_kl[Mrows*Ccn];
__device__ __align__(256) __nv_bfloat16 g_vh[Mrows*Ccn];
__device__ __align__(256) __nv_bfloat16 g_vl[Mrows*Ccn];
__device__ __align__(256) __nv_bfloat16 g_yh[Mrows*Ccn];
__device__ __align__(256) __nv_bfloat16 g_yl[Mrows*Ccn];
__device__ __align__(256) __nv_bfloat16 g_whi[4][Ccn*Ccn];
__device__ __align__(256) __nv_bfloat16 g_wlo[4][Ccn*Ccn];

// ---------------- helpers ----------------
__device__ __forceinline__ uint32_t smem_u32(const void* p) {
    uint32_t a;
    asm("{ .reg .u64 t; cvta.to.shared.u64 t, %1; cvt.u32.u64 %0, t; }"
        : "=r"(a) : "l"(p));
    return a;
}

__device__ __forceinline__ void cp16(uint32_t dst, const void* src) {
    asm volatile("cp.async.cg.shared.global [%0], [%1], 16;"
                 :: "r"(dst), "l"(src));
}

__device__ __forceinline__ void ldsm_x4(uint32_t addr, uint32_t& r0, uint32_t& r1,
                                        uint32_t& r2, uint32_t& r3) {
    asm volatile("ldmatrix.sync.aligned.m8n8.x4.shared.b16 {%0,%1,%2,%3}, [%4];"
                 : "=r"(r0), "=r"(r1), "=r"(r2), "=r"(r3) : "r"(addr));
}

__device__ __forceinline__ void ldsm_x4t(uint32_t addr, uint32_t& r0, uint32_t& r1,
                                         uint32_t& r2, uint32_t& r3) {
    asm volatile("ldmatrix.sync.aligned.m8n8.x4.trans.shared.b16 {%0,%1,%2,%3}, [%4];"
                 : "=r"(r0), "=r"(r1), "=r"(r2), "=r"(r3) : "r"(addr));
}

__device__ __forceinline__ void mma_bf16(float* d, uint32_t a0, uint32_t a1,
                                         uint32_t a2, uint32_t a3,
                                         uint32_t b0, uint32_t b1) {
    asm volatile(
        "mma.sync.aligned.m16n8k16.row.col.f32.bf16.bf16.f32 "
        "{%0,%1,%2,%3}, {%4,%5,%6,%7}, {%8,%9}, {%0,%1,%2,%3};"
        : "+f"(d[0]), "+f"(d[1]), "+f"(d[2]), "+f"(d[3])
        : "r"(a0), "r"(a1), "r"(a2), "r"(a3), "r"(b0), "r"(b1));
}

__device__ __forceinline__ void split2(float x, float y, uint32_t& hi, uint32_t& lo) {
    __nv_bfloat16 hx = __float2bfloat16(x), hy = __float2bfloat16(y);
    __nv_bfloat16 lx = __float2bfloat16(x - __bfloat162float(hx));
    __nv_bfloat16 ly = __float2bfloat16(y - __bfloat162float(hy));
    __nv_bfloat162 H = __halves2bfloat162(hx, hy);
    __nv_bfloat162 L = __halves2bfloat162(lx, ly);
    hi = *(uint32_t*)&H;
    lo = *(uint32_t*)&L;
}

// ---------------------------------------------------------------------------
// bf16 split for x (+ invfreq init in block 0)
// ---------------------------------------------------------------------------
__global__ void split_bf16(const float* __restrict__ X,
                           __nv_bfloat16* __restrict__ H,
                           __nv_bfloat16* __restrict__ L, int n4, int do_init)
{
    if (do_init && blockIdx.x == 0 && threadIdx.x < Dd / 2)
        g_invfreq[threadIdx.x] =
            (float)exp(-((double)(2 * threadIdx.x) / (double)Dd) * log(10000.0));

    int i = blockIdx.x * blockDim.x + threadIdx.x;
    if (i >= n4) return;
    float4 v = ((const float4*)X)[i];
    __nv_bfloat16 h0 = __float2bfloat16(v.x);
    __nv_bfloat16 h1 = __float2bfloat16(v.y);
    __nv_bfloat16 h2 = __float2bfloat16(v.z);
    __nv_bfloat16 h3 = __float2bfloat16(v.w);
    __nv_bfloat16 l0 = __float2bfloat16(v.x - __bfloat162float(h0));
    __nv_bfloat16 l1 = __float2bfloat16(v.y - __bfloat162float(h1));
    __nv_bfloat16 l2 = __float2bfloat16(v.z - __bfloat162float(h2));
    __nv_bfloat16 l3 = __float2bfloat16(v.w - __bfloat162float(h3));
    __nv_bfloat162* Hp = (__nv_bfloat162*)H;
    __nv_bfloat162* Lp = (__nv_bfloat162*)L;
    Hp[2*i]   = __halves2bfloat162(h0, h1);
    Hp[2*i+1] = __halves2bfloat162(h2, h3);
    Lp[2*i]   = __halves2bfloat162(l0, l1);
    Lp[2*i+1] = __halves2bfloat162(l2, l3);
}

// fused split of all 4 weight matrices (one launch)
__global__ void split_w4(const float* __restrict__ W0, const float* __restrict__ W1,
                         const float* __restrict__ W2, const float* __restrict__ W3,
                         __nv_bfloat16* __restrict__ H, __nv_bfloat16* __restrict__ L,
                         int n4)
{
    int zi = blockIdx.y;
    const float* X = (zi == 0) ? W0 : (zi == 1) ? W1 : (zi == 2) ? W2 : W3;
    __nv_bfloat16* Hd = H + (size_t)zi * (size_t)Ccn * Ccn;
    __nv_bfloat16* Ld = L + (size_t)zi * (size_t)Ccn * Ccn;

    int i = blockIdx.x * blockDim.x + threadIdx.x;
    if (i >= n4) return;
    float4 v = ((const float4*)X)[i];
    __nv_bfloat16 h0 = __float2bfloat16(v.x);
    __nv_bfloat16 h1 = __float2bfloat16(v.y);
    __nv_bfloat16 h2 = __float2bfloat16(v.z);
    __nv_bfloat16 h3 = __float2bfloat16(v.w);
    __nv_bfloat16 l0 = __float2bfloat16(v.x - __bfloat162float(h0));
    __nv_bfloat16 l1 = __float2bfloat16(v.y - __bfloat162float(h1));
    __nv_bfloat16 l2 = __float2bfloat16(v.z - __bfloat162float(h2));
    __nv_bfloat16 l3 = __float2bfloat16(v.w - __bfloat162float(h3));
    __nv_bfloat162* Hp = (__nv_bfloat162*)Hd;
    __nv_bfloat162* Lp = (__nv_bfloat162*)Ld;
    Hp[2*i]   = __halves2bfloat162(h0, h1);
    Hp[2*i+1] = __halves2bfloat162(h2, h3);
    Lp[2*i]   = __halves2bfloat162(l0, l1);
    Lp[2*i+1] = __halves2bfloat162(l2, l3);
}

// ---------------------------------------------------------------------------
// mma.sync bf16 3-term GEMM (NT), fat warp tiles:
// Tile 128x128, 128 threads (4 warps x 32rows x 128cols), K-chunk 32,
// 3-stage pipeline, 96KB smem, 2 CTAs/SM, <=255 regs.
// ---------------------------------------------------------------------------
#define STAGE_BYTES 32768
#define GEMM_SMEM   (3*STAGE_BYTES)

__global__ __launch_bounds__(128, 2)
void gemm3_mma(const __nv_bfloat16* __restrict__ Ahi,
               const __nv_bfloat16* __restrict__ Alo,
               const __nv_bfloat16* __restrict__ Bh_base,
               const __nv_bfloat16* __restrict__ Bl_base,
               float* __restrict__ C,
               __nv_bfloat16* __restrict__ QH, __nv_bfloat16* __restrict__ QL,
               __nv_bfloat16* __restrict__ KH, __nv_bfloat16* __restrict__ KL,
               __nv_bfloat16* __restrict__ VH, __nv_bfloat16* __restrict__ VL,
               int M, int N, int K, int mode)
{
    extern __shared__ char smraw[];
    const uint32_t smb = smem_u32(smraw);

    const int tid  = threadIdx.x;
    const int lane = tid & 31;
    const int wm   = tid >> 5;       // 4 warps along M (32 rows each), full N
    const int m0   = blockIdx.y << 7;
    const int n0   = blockIdx.x << 7;
    const int z    = blockIdx.z;
    const int NC   = K >> 5;

    const __nv_bfloat16* Bhi = Bh_base + (size_t)z * K * N;
    const __nv_bfloat16* Blo = Bl_base + (size_t)z * K * N;
    const __nv_bfloat16* gsrc[4] = {Ahi, Alo, Bhi, Blo};

    auto load_stage = [&](int c, int s) {
        const int kk = c << 5;
        const uint32_t st = smb + (uint32_t)s * STAGE_BYTES;
#pragma unroll
        for (int buf = 0; buf < 4; buf++) {
            const __nv_bfloat16* src = gsrc[buf];
            const int rbase = (buf < 2) ? m0 : n0;
#pragma unroll
            for (int t = 0; t < 4; t++) {
                int cidx = tid + (t << 7);          // 0..511 = 128 rows x 4 granules
                int r = cidx >> 2;
                uint32_t cb = (uint32_t)(cidx & 3) << 4;
                uint32_t dst = st + (uint32_t)buf * 8192 + (r << 6)
                             + (cb ^ (((r >> 1) & 3) << 4));
                cp16(dst, src + (size_t)(rbase + r) * K + kk + ((cidx & 3) << 3));
            }
        }
    };

    float acc[2][16][4];
#pragma unroll
    for (int mi = 0; mi < 2; mi++)
#pragma unroll
        for (int ni = 0; ni < 16; ni++)
#pragma unroll
            for (int j = 0; j < 4; j++) acc[mi][ni][j] = 0.0f;

    load_stage(0, 0);
    asm volatile("cp.async.commit_group;" ::: "memory");
    load_stage(1, 1);
    asm volatile("cp.async.commit_group;" ::: "memory");

    const int a_row = (wm << 5) + (lane & 15);
    const uint32_t a_cb = (uint32_t)((lane >> 4) << 4);
    const int b_row_in = (lane & 7) + ((lane >> 4) << 3);
    const uint32_t b_cb = (uint32_t)(((lane >> 3) & 1) << 4);

    for (int c = 0; c < NC; c++) {
        asm volatile("cp.async.wait_group 1;" ::: "memory");
        __syncthreads();
        if (c + 2 < NC) load_stage(c + 2, (c + 2) % 3);
        asm volatile("cp.async.commit_group;" ::: "memory");

        const uint32_t st = smb + (uint32_t)(c % 3) * STAGE_BYTES;
        const uint32_t sAhi = st,           sAlo = st + 8192;
        const uint32_t sBhi = st + 16384,   sBlo = st + 24576;

#pragma unroll
        for (int kq = 0; kq < 2; kq++) {
            const uint32_t kb = (uint32_t)kq << 5;

            uint32_t ah[2][4], al[2][4];
#pragma unroll
            for (int mi = 0; mi < 2; mi++) {
                int row = a_row + (mi << 4);
                uint32_t off = (uint32_t)(row << 6)
                             + ((kb + a_cb) ^ (((row >> 1) & 3) << 4));
                ldsm_x4(sAhi + off, ah[mi][0], ah[mi][1], ah[mi][2], ah[mi][3]);
                ldsm_x4(sAlo + off, al[mi][0], al[mi][1], al[mi][2], al[mi][3]);
            }

#pragma unroll
            for (int np = 0; np < 8; np++) {
                int row = b_row_in + (np << 4);
                uint32_t off = (uint32_t)(row << 6)
                             + ((kb + b_cb) ^ (((row >> 1) & 3) << 4));
                uint32_t kh[4], kl[4];
                ldsm_x4(sBhi + off, kh[0], kh[1], kh[2], kh[3]);
                ldsm_x4(sBlo + off, kl[0], kl[1], kl[2], kl[3]);
#pragma unroll
                for (int mi = 0; mi < 2; mi++) {
                    mma_bf16(acc[mi][2*np],   ah[mi][0],ah[mi][1],ah[mi][2],ah[mi][3], kh[0],kh[1]);
                    mma_bf16(acc[mi][2*np],   ah[mi][0],ah[mi][1],ah[mi][2],ah[mi][3], kl[0],kl[1]);
                    mma_bf16(acc[mi][2*np],   al[mi][0],al[mi][1],al[mi][2],al[mi][3], kh[0],kh[1]);
                    mma_bf16(acc[mi][2*np+1], ah[mi][0],ah[mi][1],ah[mi][2],ah[mi][3], kh[2],kh[3]);
                    mma_bf16(acc[mi][2*np+1], ah[mi][0],ah[mi][1],ah[mi][2],ah[mi][3], kl[2],kl[3]);
                    mma_bf16(acc[mi][2*np+1], al[mi][0],al[mi][1],al[mi][2],al[mi][3], kh[2],kh[3]);
                }
            }
        }
    }

    // ---- epilogue ----
    if (mode == 1) {
#pragma unroll
        for (int mi = 0; mi < 2; mi++) {
            int r0g = m0 + (wm << 5) + (mi << 4) + (lane >> 2);
#pragma unroll
            for (int ni = 0; ni < 16; ni++) {
                int col = n0 + (ni << 3) + ((lane & 3) << 1);
                *(float2*)(C + (size_t)r0g * N + col) =
                    make_float2(acc[mi][ni][0], acc[mi][ni][1]);
                *(float2*)(C + (size_t)(r0g + 8) * N + col) =
                    make_float2(acc[mi][ni][2], acc[mi][ni][3]);
            }
        }
        return;
    }

    if (z == 2) {   // V: direct bf16 hi/lo split
#pragma unroll
        for (int mi = 0; mi < 2; mi++) {
            int r0g = m0 + (wm << 5) + (mi << 4) + (lane >> 2);
#pragma unroll
            for (int ni = 0; ni < 16; ni++) {
                int col = n0 + (ni << 3) + ((lane & 3) << 1);
                uint32_t hi, lo;
                split2(acc[mi][ni][0], acc[mi][ni][1], hi, lo);
                *(uint32_t*)(VH + (size_t)r0g * N + col) = hi;
                *(uint32_t*)(VL + (size_t)r0g * N + col) = lo;
                split2(acc[mi][ni][2], acc[mi][ni][3], hi, lo);
                *(uint32_t*)(VH + (size_t)(r0g + 8) * N + col) = hi;
                *(uint32_t*)(VL + (size_t)(r0g + 8) * N + col) = lo;
            }
        }
        return;
    }

    // z = 0 (Q) or 1 (K): double rotary fused via smem exchange (R8 style).
    __syncthreads();
    float* sred = (float*)smraw;           // 128 x 132 fp32
#pragma unroll
    for (int mi = 0; mi < 2; mi++) {
        int r0 = (wm << 5) + (mi << 4) + (lane >> 2);
#pragma unroll
        for (int ni = 0; ni < 16; ni++) {
            int col = (ni << 3) + ((lane & 3) << 1);
            sred[r0 * 132 + col]       = acc[mi][ni][0];
            sred[r0 * 132 + col + 1]   = acc[mi][ni][1];
            sred[(r0+8) * 132 + col]   = acc[mi][ni][2];
            sred[(r0+8) * 132 + col+1] = acc[mi][ni][3];
        }
    }
    __syncthreads();

    __nv_bfloat16* H = (z == 0) ? QH : KH;
    __nv_bfloat16* L = (z == 0) ? QL : KL;
#pragma unroll 4
    for (int i = tid; i < 128 * 64; i += 128) {
        int r = i >> 6, j = i & 63;
        int m = m0 + r;
        int tpos = m & (Tt - 1);
        float f = (float)tpos * g_invfreq[j];
        float s, c;
        sincosf(f, &s, &c);
        float x1 = sred[r * 132 + j], x2 = sred[r * 132 + j + 64];
        float y1 = x1 * c + x2 * s;
        float y2 = -x1 * s + x2 * c;
        float z1 = y1 * c + y2 * s;
        float z2 = -y1 * s + y2 * c;
        __nv_bfloat16 h1 = __float2bfloat16(z1);
        __nv_bfloat16 h2 = __float2bfloat16(z2);
        size_t base = (size_t)m * N + n0 + j;
        H[base]      = h1;
        L[base]      = __float2bfloat16(z1 - __bfloat162float(h1));
        H[base + 64] = h2;
        L[base + 64] = __float2bfloat16(z2 - __bfloat162float(h2));
    }
}

// ---------------------------------------------------------------------------
// Flash attention — exact R8 version (best known).
// BM=64, BN=32, D=128, 128 threads, 96KB smem => 2 CTAs/SM. Heavy tiles first.
// ---------------------------------------------------------------------------
#define FLASH_SMEM 98304

__global__ __launch_bounds__(128, 2)
void flash_mma(const __nv_bfloat16* __restrict__ Qh_g, const __nv_bfloat16* __restrict__ Ql_g,
               const __nv_bfloat16* __restrict__ Kh_g, const __nv_bfloat16* __restrict__ Kl_g,
               const __nv_bfloat16* __restrict__ Vh_g, const __nv_bfloat16* __restrict__ Vl_g,
               __nv_bfloat16* __restrict__ Yh_g, __nv_bfloat16* __restrict__ Yl_g)
{
    extern __shared__ char sm[];
    const uint32_t smb = smem_u32(sm);
    const uint32_t sQh = smb, sQl = smb + 16384;

    const int tid = threadIdx.x, lane = tid & 31, w = tid >> 5;
    const int q0 = (int)(gridDim.x - 1 - blockIdx.x) << 6;   // heavy first
    const int h = blockIdx.y, b = blockIdx.z;
    const int rw = w << 4;             // 4 warps x 16 rows

    const size_t qoff = ((size_t)(b * Tt + q0)) * Ccn + h * Dd;
    const char* Qhp = (const char*)(Qh_g + qoff);
    const char* Qlp = (const char*)(Ql_g + qoff);

    // Q tile: 64 rows x 256B per component
#pragma unroll
    for (int t = 0; t < 8; t++) {
        int c = tid + (t << 7);
        int r = c >> 4, cb = (c & 15) << 4;
        uint32_t off = (uint32_t)(r << 8) + (uint32_t)(cb ^ ((r & 7) << 4));
        size_t g = (size_t)r * (Ccn * 2) + cb;
        cp16(sQh + off, Qhp + g);
        cp16(sQl + off, Qlp + g);
    }

    const size_t kbase = ((size_t)(b * Tt)) * Ccn + h * Dd;

    auto load_kv = [&](int j0, int s) {
        uint32_t st = smb + 32768 + (uint32_t)s * 32768;
        const char* Khp = (const char*)(Kh_g + kbase + (size_t)j0 * Ccn);
        const char* Klp = (const char*)(Kl_g + kbase + (size_t)j0 * Ccn);
        const char* Vhp = (const char*)(Vh_g + kbase + (size_t)j0 * Ccn);
        const char* Vlp = (const char*)(Vl_g + kbase + (size_t)j0 * Ccn);
#pragma unroll
        for (int t = 0; t < 4; t++) {
            int c = tid + (t << 7);
            int r = c >> 4, cb = (c & 15) << 4;
            uint32_t off = (uint32_t)(r << 8) + (uint32_t)(cb ^ ((r & 7) << 4));
            size_t g = (size_t)r * (Ccn * 2) + cb;
            cp16(st + off,          Khp + g);
            cp16(st + 8192 + off,   Klp + g);
            cp16(st + 16384 + off,  Vhp + g);
            cp16(st + 24576 + off,  Vlp + g);
        }
    };

    const int niter = (q0 >> 5) + 2;
    load_kv(0, 0);
    asm volatile("cp.async.commit_group;" ::: "memory");
    load_kv(32, 1);
    asm volatile("cp.async.commit_group;" ::: "memory");

    float o[16][4];
#pragma unroll
    for (int nt = 0; nt < 16; nt++)
#pragma unroll
        for (int e = 0; e < 4; e++) o[nt][e] = 0.0f;
    float mr0 = -INFINITY, mr1 = -INFINITY, lr0 = 0.0f, lr1 = 0.0f;

    const float SC2 = 0.08838834764831843f * 1.4426950408889634f;

    for (int it = 0; it < niter; it++) {
        const int j0 = it << 5;
        const uint32_t st = smb + 32768 + (uint32_t)(it & 1) * 32768;

        if (it + 1 < niter) asm volatile("cp.async.wait_group 1;" ::: "memory");
        else                asm volatile("cp.async.wait_group 0;" ::: "memory");
        __syncthreads();

        const bool active = (q0 + rw + 15) >= j0;
        if (active) {
            float sa[4][4];
#pragma unroll
            for (int nt = 0; nt < 4; nt++)
#pragma unroll
                for (int e = 0; e < 4; e++) sa[nt][e] = 0.0f;

            const uint32_t sKh = st, sKl = st + 8192;
#pragma unroll
            for (int ks = 0; ks < 8; ks++) {
                int ar = rw + (lane & 15);
                uint32_t ao = (uint32_t)(ar << 8)
                    + (uint32_t)((((ks << 5) + ((lane >> 4) << 4))) ^ ((ar & 7) << 4));
                uint32_t qh[4], ql[4];
                ldsm_x4(sQh + ao, qh[0], qh[1], qh[2], qh[3]);
                ldsm_x4(sQl + ao, ql[0], ql[1], ql[2], ql[3]);
#pragma unroll
                for (int np = 0; np < 2; np++) {
                    int br = (np << 4) + ((lane >> 4) << 3) + (lane & 7);
                    uint32_t bo = (uint32_t)(br << 8)
                        + (uint32_t)((((ks << 5) + (((lane >> 3) & 1) << 4))) ^ ((br & 7) << 4));
                    uint32_t kh[4], kl[4];
                    ldsm_x4(sKh + bo, kh[0], kh[1], kh[2], kh[3]);
                    ldsm_x4(sKl + bo, kl[0], kl[1], kl[2], kl[3]);
                    mma_bf16(sa[2*np],   qh[0],qh[1],qh[2],qh[3], kh[0],kh[1]);
                    mma_bf16(sa[2*np],   qh[0],qh[1],qh[2],qh[3], kl[0],kl[1]);
                    mma_bf16(sa[2*np],   ql[0],ql[1],ql[2],ql[3], kh[0],kh[1]);
                    mma_bf16(sa[2*np+1], qh[0],qh[1],qh[2],qh[3], kh[2],kh[3]);
                    mma_bf16(sa[2*np+1], qh[0],qh[1],qh[2],qh[3], kl[2],kl[3]);
                    mma_bf16(sa[2*np+1], ql[0],ql[1],ql[2],ql[3], kh[2],kh[3]);
                }
            }

            const int r0p = q0 + rw + (lane >> 2);
            const int r1p = r0p + 8;
            if (j0 + 31 > q0 + rw) {
#pragma unroll
                for (int nt = 0; nt < 4; nt++) {
                    int c0 = j0 + (nt << 3) + ((lane & 3) << 1);
                    sa[nt][0] = (c0     <= r0p) ? sa[nt][0] * SC2 : -INFINITY;
                    sa[nt][1] = (c0 + 1 <= r0p) ? sa[nt][1] * SC2 : -INFINITY;
                    sa[nt][2] = (c0     <= r1p) ? sa[nt][2] * SC2 : -INFINITY;
                    sa[nt][3] = (c0 + 1 <= r1p) ? sa[nt][3] * SC2 : -INFINITY;
                }
            } else {
#pragma unroll
                for (int nt = 0; nt < 4; nt++)
#pragma unroll
                    for (int e = 0; e < 4; e++) sa[nt][e] *= SC2;
            }

            float mx0 = -INFINITY, mx1 = -INFINITY;
#pragma unroll
            for (int nt = 0; nt < 4; nt++) {
                mx0 = fmaxf(mx0, fmaxf(sa[nt][0], sa[nt][1]));
                mx1 = fmaxf(mx1, fmaxf(sa[nt][2], sa[nt][3]));
            }
            mx0 = fmaxf(mx0, __shfl_xor_sync(0xffffffffu, mx0, 1));
            mx0 = fmaxf(mx0, __shfl_xor_sync(0xffffffffu, mx0, 2));
            mx1 = fmaxf(mx1, __shfl_xor_sync(0xffffffffu, mx1, 1));
            mx1 = fmaxf(mx1, __shfl_xor_sync(0xffffffffu, mx1, 2));

            float mn0 = fmaxf(mr0, mx0), mn1 = fmaxf(mr1, mx1);
            float a0 = exp2f(mr0 - mn0), a1 = exp2f(mr1 - mn1);
            mr0 = mn0; mr1 = mn1;

            float s0 = 0.0f, s1 = 0.0f;
#pragma unroll
            for (int nt = 0; nt < 4; nt++) {
                sa[nt][0] = exp2f(sa[nt][0] - mn0);
                sa[nt][1] = exp2f(sa[nt][1] - mn0);
                sa[nt][2] = exp2f(sa[nt][2] - mn1);
                sa[nt][3] = exp2f(sa[nt][3] - mn1);
                s0 += sa[nt][0] + sa[nt][1];
                s1 += sa[nt][2] + sa[nt][3];
            }
            s0 += __shfl_xor_sync(0xffffffffu, s0, 1);
            s0 += __shfl_xor_sync(0xffffffffu, s0, 2);
            s1 += __shfl_xor_sync(0xffffffffu, s1, 1);
            s1 += __shfl_xor_sync(0xffffffffu, s1, 2);
            lr0 = lr0 * a0 + s0;
            lr1 = lr1 * a1 + s1;

#pragma unroll
            for (int nt = 0; nt < 16; nt++) {
                o[nt][0] *= a0; o[nt][1] *= a0;
                o[nt][2] *= a1; o[nt][3] *= a1;
            }

            // P @ V : P 16x32, V 32x128
            const uint32_t sVh = st + 16384, sVl = st + 24576;
#pragma unroll
            for (int kc = 0; kc < 2; kc++) {
                uint32_t ph[4], pl[4];
                split2(sa[2*kc][0],   sa[2*kc][1],   ph[0], pl[0]);
                split2(sa[2*kc][2],   sa[2*kc][3],   ph[1], pl[1]);
                split2(sa[2*kc+1][0], sa[2*kc+1][1], ph[2], pl[2]);
                split2(sa[2*kc+1][2], sa[2*kc+1][3], ph[3], pl[3]);

                int vr = (kc << 4) + (((lane >> 3) & 1) << 3) + (lane & 7);
#pragma unroll
                for (int np = 0; np < 8; np++) {
                    uint32_t vo = (uint32_t)(vr << 8)
                        + (uint32_t)((((np << 5) + ((lane >> 4) << 4))) ^ ((vr & 7) << 4));
                    uint32_t vh[4], vl[4];
                    ldsm_x4t(sVh + vo, vh[0], vh[1], vh[2], vh[3]);
                    ldsm_x4t(sVl + vo, vl[0], vl[1], vl[2], vl[3]);
                    mma_bf16(o[2*np],   ph[0],ph[1],ph[2],ph[3], vh[0],vh[1]);
                    mma_bf16(o[2*np],   ph[0],ph[1],ph[2],ph[3], vl[0],vl[1]);
                    mma_bf16(o[2*np],   pl[0],pl[1],pl[2],pl[3], vh[0],vh[1]);
                    mma_bf16(o[2*np+1], ph[0],ph[1],ph[2],ph[3], vh[2],vh[3]);
                    mma_bf16(o[2*np+1], ph[0],ph[1],ph[2],ph[3], vl[2],vl[3]);
                    mma_bf16(o[2*np+1], pl[0],pl[1],pl[2],pl[3], vh[2],vh[3]);
                }
            }
        }

        __syncthreads();
        if (it + 2 < niter) load_kv((it + 2) << 5, it & 1);
        asm volatile("cp.async.commit_group;" ::: "memory");
    }

    const float i0 = 1.0f / lr0, i1 = 1.0f / lr1;
    const size_t r0g = (size_t)(b * Tt + q0 + rw + (lane >> 2)) * Ccn
                     + h * Dd + ((lane & 3) << 1);
    const size_t r1g = r0g + 8 * (size_t)Ccn;
#pragma unroll
    for (int nt = 0; nt < 16; nt++) {
        uint32_t hi, lo;
        split2(o[nt][0] * i0, o[nt][1] * i0, hi, lo);
        *(uint32_t*)(Yh_g + r0g + (nt << 3)) = hi;
        *(uint32_t*)(Yl_g + r0g + (nt << 3)) = lo;
        split2(o[nt][2] * i1, o[nt][3] * i1, hi, lo);
        *(uint32_t*)(Yh_g + r1g + (nt << 3)) = hi;
        *(uint32_t*)(Yl_g + r1g + (nt << 3)) = lo;
    }
}

// ---------------------------------------------------------------------------
extern "C" void kernel_launch(void* const* d_in, const int* in_sizes, int n_in,
                              void* d_out, int out_size)
{
    (void)in_sizes; (void)n_in; (void)out_size;
    const float* x  = (const float*)d_in[0];
    const float* wq = (const float*)d_in[1];
    const float* wk = (const float*)d_in[2];
    const float* wv = (const float*)d_in[3];
    const float* wo = (const float*)d_in[4];
    float* out = (float*)d_out;

    __nv_bfloat16 *xhi, *xlo, *whi, *wlo;
    __nv_bfloat16 *qh, *ql, *kh, *kl, *vh, *vl, *yh, *yl;
    cudaGetSymbolAddress((void**)&xhi, g_xhi);
    cudaGetSymbolAddress((void**)&xlo, g_xlo);
    cudaGetSymbolAddress((void**)&whi, g_whi);
    cudaGetSymbolAddress((void**)&wlo, g_wlo);
    cudaGetSymbolAddress((void**)&qh, g_qh);
    cudaGetSymbolAddress((void**)&ql, g_ql);
    cudaGetSymbolAddress((void**)&kh, g_kh);
    cudaGetSymbolAddress((void**)&kl, g_kl);
    cudaGetSymbolAddress((void**)&vh, g_vh);
    cudaGetSymbolAddress((void**)&vl, g_vl);
    cudaGetSymbolAddress((void**)&yh, g_yh);
    cudaGetSymbolAddress((void**)&yl, g_yl);

    cudaFuncSetAttribute(gemm3_mma,
                         cudaFuncAttributeMaxDynamicSharedMemorySize, GEMM_SMEM);
    cudaFuncSetAttribute(flash_mma,
                         cudaFuncAttributeMaxDynamicSharedMemorySize, FLASH_SMEM);

    const size_t WN = (size_t)Ccn * Ccn;
    const int n4x = Mrows * Ccn / 4;
    const int n4w = (int)(WN / 4);

    split_bf16<<<n4x / 256, 256>>>(x, xhi, xlo, n4x, 1);
    split_w4<<<dim3(n4w / 256, 4), 256>>>(wq, wk, wv, wo, whi, wlo, n4w);

    // fused QKV projection + rotary + bf16 split (128-thread fat warp tiles)
    dim3 gqkv(Ccn / 128, Mrows / 128, 3);
    gemm3_mma<<<gqkv, 128, GEMM_SMEM>>>(xhi, xlo, whi, wlo,
                                        nullptr, qh, ql, kh, kl, vh, vl,
                                        Mrows, Ccn, Ccn, 0);

    // flash attention: BM=64/BN=32, 128 threads, 2 CTAs/SM (R8 version)
    flash_mma<<<dim3(Tt / 64, Hh, Bb), 128, FLASH_SMEM>>>(qh, ql, kh, kl, vh, vl, yh, yl);

    // output projection (fp32 out)
    dim3 go(Ccn / 128, Mrows / 128, 1);
    gemm3_mma<<<go, 128, GEMM_SMEM>>>(yh, yl, whi + 3 * WN, wlo + 3 * WN,
                                      out, nullptr, nullptr, nullptr, nullptr,
                                      nullptr, nullptr,
                                      Mrows, Ccn, Ccn, 1);
}

// round 15
// speedup vs baseline: 1.0250x; 1.0250x over previous
#include <cuda_runtime.h>
#include <cuda_bf16.h>
#include <math.h>
#include <stdint.h>

#define Bb 4
#define Tt 2048
#define Ccn 2048
#define Hh 16
#define Dd 128
#define Mrows (Bb*Tt)   // 8192

// ---------------- scratch (device globals) ----------------
__device__ float g_invfreq[Dd/2];

__device__ __align__(256) __nv_bfloat16 g_xhi[Mrows*Ccn];
__device__ __align__(256) __nv_bfloat16 g_xlo[Mrows*Ccn];
__device__ __align__(256) __nv_bfloat16 g_qh[Mrows*Ccn];
__device__ __align__(256) __nv_bfloat16 g_ql[Mrows*Ccn];
__device__ __align__(256) __nv_bfloat16 g_kh[Mrows*Ccn];
__device__ __align__(256) __nv_bfloat16 g_kl[Mrows*Ccn];
__device__ __align__(256) __nv_bfloat16 g_vh[Mrows*Ccn];
__device__ __align__(256) __nv_bfloat16 g_vl[Mrows*Ccn];
__device__ __align__(256) __nv_bfloat16 g_yh[Mrows*Ccn];
__device__ __align__(256) __nv_bfloat16 g_yl[Mrows*Ccn];
__device__ __align__(256) __nv_bfloat16 g_whi[4][Ccn*Ccn];
__device__ __align__(256) __nv_bfloat16 g_wlo[4][Ccn*Ccn];

// ---------------- helpers ----------------
__device__ __forceinline__ uint32_t smem_u32(const void* p) {
    uint32_t a;
    asm("{ .reg .u64 t; cvta.to.shared.u64 t, %1; cvt.u32.u64 %0, t; }"
        : "=r"(a) : "l"(p));
    return a;
}

__device__ __forceinline__ void cp16(uint32_t dst, const void* src) {
    asm volatile("cp.async.cg.shared.global [%0], [%1], 16;"
                 :: "r"(dst), "l"(src));
}

__device__ __forceinline__ void ldsm_x4(uint32_t addr, uint32_t& r0, uint32_t& r1,
                                        uint32_t& r2, uint32_t& r3) {
    asm volatile("ldmatrix.sync.aligned.m8n8.x4.shared.b16 {%0,%1,%2,%3}, [%4];"
                 : "=r"(r0), "=r"(r1), "=r"(r2), "=r"(r3) : "r"(addr));
}

__device__ __forceinline__ void ldsm_x4t(uint32_t addr, uint32_t& r0, uint32_t& r1,
                                         uint32_t& r2, uint32_t& r3) {
    asm volatile("ldmatrix.sync.aligned.m8n8.x4.trans.shared.b16 {%0,%1,%2,%3}, [%4];"
                 : "=r"(r0), "=r"(r1), "=r"(r2), "=r"(r3) : "r"(addr));
}

__device__ __forceinline__ void mma_bf16(float* d, uint32_t a0, uint32_t a1,
                                         uint32_t a2, uint32_t a3,
                                         uint32_t b0, uint32_t b1) {
    asm volatile(
        "mma.sync.aligned.m16n8k16.row.col.f32.bf16.bf16.f32 "
        "{%0,%1,%2,%3}, {%4,%5,%6,%7}, {%8,%9}, {%0,%1,%2,%3};"
        : "+f"(d[0]), "+f"(d[1]), "+f"(d[2]), "+f"(d[3])
        : "r"(a0), "r"(a1), "r"(a2), "r"(a3), "r"(b0), "r"(b1));
}

__device__ __forceinline__ void split2(float x, float y, uint32_t& hi, uint32_t& lo) {
    __nv_bfloat16 hx = __float2bfloat16(x), hy = __float2bfloat16(y);
    __nv_bfloat16 lx = __float2bfloat16(x - __bfloat162float(hx));
    __nv_bfloat16 ly = __float2bfloat16(y - __bfloat162float(hy));
    __nv_bfloat162 H = __halves2bfloat162(hx, hy);
    __nv_bfloat162 L = __halves2bfloat162(lx, ly);
    hi = *(uint32_t*)&H;
    lo = *(uint32_t*)&L;
}

// ---------------------------------------------------------------------------
// bf16 split for x (+ invfreq init in block 0)
// ---------------------------------------------------------------------------
__global__ void split_bf16(const float* __restrict__ X,
                           __nv_bfloat16* __restrict__ H,
                           __nv_bfloat16* __restrict__ L, int n4, int do_init)
{
    if (do_init && blockIdx.x == 0 && threadIdx.x < Dd / 2)
        g_invfreq[threadIdx.x] =
            (float)exp(-((double)(2 * threadIdx.x) / (double)Dd) * log(10000.0));

    int i = blockIdx.x * blockDim.x + threadIdx.x;
    if (i >= n4) return;
    float4 v = ((const float4*)X)[i];
    __nv_bfloat16 h0 = __float2bfloat16(v.x);
    __nv_bfloat16 h1 = __float2bfloat16(v.y);
    __nv_bfloat16 h2 = __float2bfloat16(v.z);
    __nv_bfloat16 h3 = __float2bfloat16(v.w);
    __nv_bfloat16 l0 = __float2bfloat16(v.x - __bfloat162float(h0));
    __nv_bfloat16 l1 = __float2bfloat16(v.y - __bfloat162float(h1));
    __nv_bfloat16 l2 = __float2bfloat16(v.z - __bfloat162float(h2));
    __nv_bfloat16 l3 = __float2bfloat16(v.w - __bfloat162float(h3));
    __nv_bfloat162* Hp = (__nv_bfloat162*)H;
    __nv_bfloat162* Lp = (__nv_bfloat162*)L;
    Hp[2*i]   = __halves2bfloat162(h0, h1);
    Hp[2*i+1] = __halves2bfloat162(h2, h3);
    Lp[2*i]   = __halves2bfloat162(l0, l1);
    Lp[2*i+1] = __halves2bfloat162(l2, l3);
}

// fused split of all 4 weight matrices (one launch)
__global__ void split_w4(const float* __restrict__ W0, const float* __restrict__ W1,
                         const float* __restrict__ W2, const float* __restrict__ W3,
                         __nv_bfloat16* __restrict__ H, __nv_bfloat16* __restrict__ L,
                         int n4)
{
    int zi = blockIdx.y;
    const float* X = (zi == 0) ? W0 : (zi == 1) ? W1 : (zi == 2) ? W2 : W3;
    __nv_bfloat16* Hd = H + (size_t)zi * (size_t)Ccn * Ccn;
    __nv_bfloat16* Ld = L + (size_t)zi * (size_t)Ccn * Ccn;

    int i = blockIdx.x * blockDim.x + threadIdx.x;
    if (i >= n4) return;
    float4 v = ((const float4*)X)[i];
    __nv_bfloat16 h0 = __float2bfloat16(v.x);
    __nv_bfloat16 h1 = __float2bfloat16(v.y);
    __nv_bfloat16 h2 = __float2bfloat16(v.z);
    __nv_bfloat16 h3 = __float2bfloat16(v.w);
    __nv_bfloat16 l0 = __float2bfloat16(v.x - __bfloat162float(h0));
    __nv_bfloat16 l1 = __float2bfloat16(v.y - __bfloat162float(h1));
    __nv_bfloat16 l2 = __float2bfloat16(v.z - __bfloat162float(h2));
    __nv_bfloat16 l3 = __float2bfloat16(v.w - __bfloat162float(h3));
    __nv_bfloat162* Hp = (__nv_bfloat162*)Hd;
    __nv_bfloat162* Lp = (__nv_bfloat162*)Ld;
    Hp[2*i]   = __halves2bfloat162(h0, h1);
    Hp[2*i+1] = __halves2bfloat162(h2, h3);
    Lp[2*i]   = __halves2bfloat162(l0, l1);
    Lp[2*i+1] = __halves2bfloat162(l2, l3);
}

// ---------------------------------------------------------------------------
// mma.sync bf16 3-term GEMM (NT) — R8 config; mainloop wait relaxed to
// wait_group 2 (stage c already guaranteed by iter c-1's wait).
// Tile 128x128, K-chunk 32, 3-stage pipeline, 256 threads, 2 CTAs/SM.
// ---------------------------------------------------------------------------
#define STAGE_BYTES 32768
#define GEMM_SMEM   (3*STAGE_BYTES)

__global__ __launch_bounds__(256, 2)
void gemm3_mma(const __nv_bfloat16* __restrict__ Ahi,
               const __nv_bfloat16* __restrict__ Alo,
               const __nv_bfloat16* __restrict__ Bh_base,
               const __nv_bfloat16* __restrict__ Bl_base,
               float* __restrict__ C,
               __nv_bfloat16* __restrict__ QH, __nv_bfloat16* __restrict__ QL,
               __nv_bfloat16* __restrict__ KH, __nv_bfloat16* __restrict__ KL,
               __nv_bfloat16* __restrict__ VH, __nv_bfloat16* __restrict__ VL,
               int M, int N, int K, int mode)
{
    extern __shared__ char smraw[];
    const uint32_t smb = smem_u32(smraw);

    const int tid  = threadIdx.x;
    const int lane = tid & 31;
    const int w    = tid >> 5;
    const int wm   = w & 3;
    const int wn   = w >> 2;
    const int m0   = blockIdx.y << 7;
    const int n0   = blockIdx.x << 7;
    const int z    = blockIdx.z;
    const int NC   = K >> 5;

    const __nv_bfloat16* Bhi = Bh_base + (size_t)z * K * N;
    const __nv_bfloat16* Blo = Bl_base + (size_t)z * K * N;
    const __nv_bfloat16* gsrc[4] = {Ahi, Alo, Bhi, Blo};

    auto load_stage = [&](int c, int s) {
        const int kk = c << 5;
        const uint32_t st = smb + (uint32_t)s * STAGE_BYTES;
#pragma unroll
        for (int buf = 0; buf < 4; buf++) {
            const __nv_bfloat16* src = gsrc[buf];
            const int rbase = (buf < 2) ? m0 : n0;
#pragma unroll
            for (int t = 0; t < 2; t++) {
                int cidx = tid + (t << 8);
                int r = cidx >> 2;
                uint32_t cb = (uint32_t)(cidx & 3) << 4;
                uint32_t dst = st + (uint32_t)buf * 8192 + (r << 6)
                             + (cb ^ (((r >> 1) & 3) << 4));
                cp16(dst, src + (size_t)(rbase + r) * K + kk + ((cidx & 3) << 3));
            }
        }
    };

    float acc[2][8][4];
#pragma unroll
    for (int mi = 0; mi < 2; mi++)
#pragma unroll
        for (int ni = 0; ni < 8; ni++)
#pragma unroll
            for (int j = 0; j < 4; j++) acc[mi][ni][j] = 0.0f;

    load_stage(0, 0);
    asm volatile("cp.async.commit_group;" ::: "memory");
    load_stage(1, 1);
    asm volatile("cp.async.commit_group;" ::: "memory");

    const int a_row = (wm << 5) + (lane & 15);
    const uint32_t a_cb = (uint32_t)((lane >> 4) << 4);
    const int b_row = (wn << 6) + (lane & 7) + ((lane >> 4) << 3);
    const uint32_t b_cb = (uint32_t)(((lane >> 3) & 1) << 4);

    for (int c = 0; c < NC; c++) {
        __syncthreads();   // all warps done with slot (c+2)%3 contents
        if (c + 2 < NC) load_stage(c + 2, (c + 2) % 3);
        asm volatile("cp.async.commit_group;" ::: "memory");
        // pending: {g_c, g_{c+1}, g_{c+2}} worst case; need only stage c.
        asm volatile("cp.async.wait_group 2;" ::: "memory");
        __syncthreads();   // stage c visible to all warps

        const uint32_t st = smb + (uint32_t)(c % 3) * STAGE_BYTES;
        const uint32_t sAhi = st,           sAlo = st + 8192;
        const uint32_t sBhi = st + 16384,   sBlo = st + 24576;

#pragma unroll
        for (int kq = 0; kq < 2; kq++) {
            const uint32_t kb = (uint32_t)kq << 5;

            uint32_t ah[2][4], al[2][4];
#pragma unroll
            for (int mi = 0; mi < 2; mi++) {
                int row = a_row + (mi << 4);
                uint32_t off = (uint32_t)(row << 6)
                             + ((kb + a_cb) ^ (((row >> 1) & 3) << 4));
                ldsm_x4(sAhi + off, ah[mi][0], ah[mi][1], ah[mi][2], ah[mi][3]);
                ldsm_x4(sAlo + off, al[mi][0], al[mi][1], al[mi][2], al[mi][3]);
            }

#pragma unroll
            for (int np = 0; np < 4; np++) {
                int row = b_row + (np << 4);
                uint32_t off = (uint32_t)(row << 6)
                             + ((kb + b_cb) ^ (((row >> 1) & 3) << 4));
                uint32_t kh[4], kl[4];
                ldsm_x4(sBhi + off, kh[0], kh[1], kh[2], kh[3]);
                ldsm_x4(sBlo + off, kl[0], kl[1], kl[2], kl[3]);
#pragma unroll
                for (int mi = 0; mi < 2; mi++) {
                    mma_bf16(acc[mi][2*np],   ah[mi][0],ah[mi][1],ah[mi][2],ah[mi][3], kh[0],kh[1]);
                    mma_bf16(acc[mi][2*np],   ah[mi][0],ah[mi][1],ah[mi][2],ah[mi][3], kl[0],kl[1]);
                    mma_bf16(acc[mi][2*np],   al[mi][0],al[mi][1],al[mi][2],al[mi][3], kh[0],kh[1]);
                    mma_bf16(acc[mi][2*np+1], ah[mi][0],ah[mi][1],ah[mi][2],ah[mi][3], kh[2],kh[3]);
                    mma_bf16(acc[mi][2*np+1], ah[mi][0],ah[mi][1],ah[mi][2],ah[mi][3], kl[2],kl[3]);
                    mma_bf16(acc[mi][2*np+1], al[mi][0],al[mi][1],al[mi][2],al[mi][3], kh[2],kh[3]);
                }
            }
        }
    }

    // ---- epilogue ----
    if (mode == 1) {
#pragma unroll
        for (int mi = 0; mi < 2; mi++) {
            int r0g = m0 + (wm << 5) + (mi << 4) + (lane >> 2);
#pragma unroll
            for (int ni = 0; ni < 8; ni++) {
                int col = n0 + (wn << 6) + (ni << 3) + ((lane & 3) << 1);
                *(float2*)(C + (size_t)r0g * N + col) =
                    make_float2(acc[mi][ni][0], acc[mi][ni][1]);
                *(float2*)(C + (size_t)(r0g + 8) * N + col) =
                    make_float2(acc[mi][ni][2], acc[mi][ni][3]);
            }
        }
        return;
    }

    if (z == 2) {   // V: direct bf16 hi/lo split
#pragma unroll
        for (int mi = 0; mi < 2; mi++) {
            int r0g = m0 + (wm << 5) + (mi << 4) + (lane >> 2);
#pragma unroll
            for (int ni = 0; ni < 8; ni++) {
                int col = n0 + (wn << 6) + (ni << 3) + ((lane & 3) << 1);
                uint32_t hi, lo;
                split2(acc[mi][ni][0], acc[mi][ni][1], hi, lo);
                *(uint32_t*)(VH + (size_t)r0g * N + col) = hi;
                *(uint32_t*)(VL + (size_t)r0g * N + col) = lo;
                split2(acc[mi][ni][2], acc[mi][ni][3], hi, lo);
                *(uint32_t*)(VH + (size_t)(r0g + 8) * N + col) = hi;
                *(uint32_t*)(VL + (size_t)(r0g + 8) * N + col) = lo;
            }
        }
        return;
    }

    // z = 0 (Q) or 1 (K): double rotary fused via smem exchange (R8 version).
    __syncthreads();
    float* sred = (float*)smraw;           // 128 x 132 fp32
#pragma unroll
    for (int mi = 0; mi < 2; mi++) {
        int r0 = (wm << 5) + (mi << 4) + (lane >> 2);
#pragma unroll
        for (int ni = 0; ni < 8; ni++) {
            int col = (wn << 6) + (ni << 3) + ((lane & 3) << 1);
            sred[r0 * 132 + col]       = acc[mi][ni][0];
            sred[r0 * 132 + col + 1]   = acc[mi][ni][1];
            sred[(r0+8) * 132 + col]   = acc[mi][ni][2];
            sred[(r0+8) * 132 + col+1] = acc[mi][ni][3];
        }
    }
    __syncthreads();

    __nv_bfloat16* H = (z == 0) ? QH : KH;
    __nv_bfloat16* L = (z == 0) ? QL : KL;
#pragma unroll 4
    for (int i = tid; i < 128 * 64; i += 256) {
        int r = i >> 6, j = i & 63;
        int m = m0 + r;
        int tpos = m & (Tt - 1);
        float f = (float)tpos * g_invfreq[j];
        float s, c;
        sincosf(f, &s, &c);
        float x1 = sred[r * 132 + j], x2 = sred[r * 132 + j + 64];
        float y1 = x1 * c + x2 * s;
        float y2 = -x1 * s + x2 * c;
        float z1 = y1 * c + y2 * s;
        float z2 = -y1 * s + y2 * c;
        __nv_bfloat16 h1 = __float2bfloat16(z1);
        __nv_bfloat16 h2 = __float2bfloat16(z2);
        size_t base = (size_t)m * N + n0 + j;
        H[base]      = h1;
        L[base]      = __float2bfloat16(z1 - __bfloat162float(h1));
        H[base + 64] = h2;
        L[base + 64] = __float2bfloat16(z2 - __bfloat162float(h2));
    }
}

// ---------------------------------------------------------------------------
// Flash attention — exact R8 version (best known).
// BM=64, BN=32, D=128, 128 threads, 96KB smem => 2 CTAs/SM. Heavy tiles first.
// ---------------------------------------------------------------------------
#define FLASH_SMEM 98304

__global__ __launch_bounds__(128, 2)
void flash_mma(const __nv_bfloat16* __restrict__ Qh_g, const __nv_bfloat16* __restrict__ Ql_g,
               const __nv_bfloat16* __restrict__ Kh_g, const __nv_bfloat16* __restrict__ Kl_g,
               const __nv_bfloat16* __restrict__ Vh_g, const __nv_bfloat16* __restrict__ Vl_g,
               __nv_bfloat16* __restrict__ Yh_g, __nv_bfloat16* __restrict__ Yl_g)
{
    extern __shared__ char sm[];
    const uint32_t smb = smem_u32(sm);
    const uint32_t sQh = smb, sQl = smb + 16384;

    const int tid = threadIdx.x, lane = tid & 31, w = tid >> 5;
    const int q0 = (int)(gridDim.x - 1 - blockIdx.x) << 6;   // heavy first
    const int h = blockIdx.y, b = blockIdx.z;
    const int rw = w << 4;             // 4 warps x 16 rows

    const size_t qoff = ((size_t)(b * Tt + q0)) * Ccn + h * Dd;
    const char* Qhp = (const char*)(Qh_g + qoff);
    const char* Qlp = (const char*)(Ql_g + qoff);

    // Q tile: 64 rows x 256B per component
#pragma unroll
    for (int t = 0; t < 8; t++) {
        int c = tid + (t << 7);
        int r = c >> 4, cb = (c & 15) << 4;
        uint32_t off = (uint32_t)(r << 8) + (uint32_t)(cb ^ ((r & 7) << 4));
        size_t g = (size_t)r * (Ccn * 2) + cb;
        cp16(sQh + off, Qhp + g);
        cp16(sQl + off, Qlp + g);
    }

    const size_t kbase = ((size_t)(b * Tt)) * Ccn + h * Dd;

    auto load_kv = [&](int j0, int s) {
        uint32_t st = smb + 32768 + (uint32_t)s * 32768;
        const char* Khp = (const char*)(Kh_g + kbase + (size_t)j0 * Ccn);
        const char* Klp = (const char*)(Kl_g + kbase + (size_t)j0 * Ccn);
        const char* Vhp = (const char*)(Vh_g + kbase + (size_t)j0 * Ccn);
        const char* Vlp = (const char*)(Vl_g + kbase + (size_t)j0 * Ccn);
#pragma unroll
        for (int t = 0; t < 4; t++) {
            int c = tid + (t << 7);
            int r = c >> 4, cb = (c & 15) << 4;
            uint32_t off = (uint32_t)(r << 8) + (uint32_t)(cb ^ ((r & 7) << 4));
            size_t g = (size_t)r * (Ccn * 2) + cb;
            cp16(st + off,          Khp + g);
            cp16(st + 8192 + off,   Klp + g);
            cp16(st + 16384 + off,  Vhp + g);
            cp16(st + 24576 + off,  Vlp + g);
        }
    };

    const int niter = (q0 >> 5) + 2;
    load_kv(0, 0);
    asm volatile("cp.async.commit_group;" ::: "memory");
    load_kv(32, 1);
    asm volatile("cp.async.commit_group;" ::: "memory");

    float o[16][4];
#pragma unroll
    for (int nt = 0; nt < 16; nt++)
#pragma unroll
        for (int e = 0; e < 4; e++) o[nt][e] = 0.0f;
    float mr0 = -INFINITY, mr1 = -INFINITY, lr0 = 0.0f, lr1 = 0.0f;

    const float SC2 = 0.08838834764831843f * 1.4426950408889634f;

    for (int it = 0; it < niter; it++) {
        const int j0 = it << 5;
        const uint32_t st = smb + 32768 + (uint32_t)(it & 1) * 32768;

        if (it + 1 < niter) asm volatile("cp.async.wait_group 1;" ::: "memory");
        else                asm volatile("cp.async.wait_group 0;" ::: "memory");
        __syncthreads();

        const bool active = (q0 + rw + 15) >= j0;
        if (active) {
            float sa[4][4];
#pragma unroll
            for (int nt = 0; nt < 4; nt++)
#pragma unroll
                for (int e = 0; e < 4; e++) sa[nt][e] = 0.0f;

            const uint32_t sKh = st, sKl = st + 8192;
#pragma unroll
            for (int ks = 0; ks < 8; ks++) {
                int ar = rw + (lane & 15);
                uint32_t ao = (uint32_t)(ar << 8)
                    + (uint32_t)((((ks << 5) + ((lane >> 4) << 4))) ^ ((ar & 7) << 4));
                uint32_t qh[4], ql[4];
                ldsm_x4(sQh + ao, qh[0], qh[1], qh[2], qh[3]);
                ldsm_x4(sQl + ao, ql[0], ql[1], ql[2], ql[3]);
#pragma unroll
                for (int np = 0; np < 2; np++) {
                    int br = (np << 4) + ((lane >> 4) << 3) + (lane & 7);
                    uint32_t bo = (uint32_t)(br << 8)
                        + (uint32_t)((((ks << 5) + (((lane >> 3) & 1) << 4))) ^ ((br & 7) << 4));
                    uint32_t kh[4], kl[4];
                    ldsm_x4(sKh + bo, kh[0], kh[1], kh[2], kh[3]);
                    ldsm_x4(sKl + bo, kl[0], kl[1], kl[2], kl[3]);
                    mma_bf16(sa[2*np],   qh[0],qh[1],qh[2],qh[3], kh[0],kh[1]);
                    mma_bf16(sa[2*np],   qh[0],qh[1],qh[2],qh[3], kl[0],kl[1]);
                    mma_bf16(sa[2*np],   ql[0],ql[1],ql[2],ql[3], kh[0],kh[1]);
                    mma_bf16(sa[2*np+1], qh[0],qh[1],qh[2],qh[3], kh[2],kh[3]);
                    mma_bf16(sa[2*np+1], qh[0],qh[1],qh[2],qh[3], kl[2],kl[3]);
                    mma_bf16(sa[2*np+1], ql[0],ql[1],ql[2],ql[3], kh[2],kh[3]);
                }
            }

            const int r0p = q0 + rw + (lane >> 2);
            const int r1p = r0p + 8;
            if (j0 + 31 > q0 + rw) {
#pragma unroll
                for (int nt = 0; nt < 4; nt++) {
                    int c0 = j0 + (nt << 3) + ((lane & 3) << 1);
                    sa[nt][0] = (c0     <= r0p) ? sa[nt][0] * SC2 : -INFINITY;
                    sa[nt][1] = (c0 + 1 <= r0p) ? sa[nt][1] * SC2 : -INFINITY;
                    sa[nt][2] = (c0     <= r1p) ? sa[nt][2] * SC2 : -INFINITY;
                    sa[nt][3] = (c0 + 1 <= r1p) ? sa[nt][3] * SC2 : -INFINITY;
                }
            } else {
#pragma unroll
                for (int nt = 0; nt < 4; nt++)
#pragma unroll
                    for (int e = 0; e < 4; e++) sa[nt][e] *= SC2;
            }

            float mx0 = -INFINITY, mx1 = -INFINITY;
#pragma unroll
            for (int nt = 0; nt < 4; nt++) {
                mx0 = fmaxf(mx0, fmaxf(sa[nt][0], sa[nt][1]));
                mx1 = fmaxf(mx1, fmaxf(sa[nt][2], sa[nt][3]));
            }
            mx0 = fmaxf(mx0, __shfl_xor_sync(0xffffffffu, mx0, 1));
            mx0 = fmaxf(mx0, __shfl_xor_sync(0xffffffffu, mx0, 2));
            mx1 = fmaxf(mx1, __shfl_xor_sync(0xffffffffu, mx1, 1));
            mx1 = fmaxf(mx1, __shfl_xor_sync(0xffffffffu, mx1, 2));

            float mn0 = fmaxf(mr0, mx0), mn1 = fmaxf(mr1, mx1);
            float a0 = exp2f(mr0 - mn0), a1 = exp2f(mr1 - mn1);
            mr0 = mn0; mr1 = mn1;

            float s0 = 0.0f, s1 = 0.0f;
#pragma unroll
            for (int nt = 0; nt < 4; nt++) {
                sa[nt][0] = exp2f(sa[nt][0] - mn0);
                sa[nt][1] = exp2f(sa[nt][1] - mn0);
                sa[nt][2] = exp2f(sa[nt][2] - mn1);
                sa[nt][3] = exp2f(sa[nt][3] - mn1);
                s0 += sa[nt][0] + sa[nt][1];
                s1 += sa[nt][2] + sa[nt][3];
            }
            s0 += __shfl_xor_sync(0xffffffffu, s0, 1);
            s0 += __shfl_xor_sync(0xffffffffu, s0, 2);
            s1 += __shfl_xor_sync(0xffffffffu, s1, 1);
            s1 += __shfl_xor_sync(0xffffffffu, s1, 2);
            lr0 = lr0 * a0 + s0;
            lr1 = lr1 * a1 + s1;

#pragma unroll
            for (int nt = 0; nt < 16; nt++) {
                o[nt][0] *= a0; o[nt][1] *= a0;
                o[nt][2] *= a1; o[nt][3] *= a1;
            }

            // P @ V : P 16x32, V 32x128
            const uint32_t sVh = st + 16384, sVl = st + 24576;
#pragma unroll
            for (int kc = 0; kc < 2; kc++) {
                uint32_t ph[4], pl[4];
                split2(sa[2*kc][0],   sa[2*kc][1],   ph[0], pl[0]);
                split2(sa[2*kc][2],   sa[2*kc][3],   ph[1], pl[1]);
                split2(sa[2*kc+1][0], sa[2*kc+1][1], ph[2], pl[2]);
                split2(sa[2*kc+1][2], sa[2*kc+1][3], ph[3], pl[3]);

                int vr = (kc << 4) + (((lane >> 3) & 1) << 3) + (lane & 7);
#pragma unroll
                for (int np = 0; np < 8; np++) {
                    uint32_t vo = (uint32_t)(vr << 8)
                        + (uint32_t)((((np << 5) + ((lane >> 4) << 4))) ^ ((vr & 7) << 4));
                    uint32_t vh[4], vl[4];
                    ldsm_x4t(sVh + vo, vh[0], vh[1], vh[2], vh[3]);
                    ldsm_x4t(sVl + vo, vl[0], vl[1], vl[2], vl[3]);
                    mma_bf16(o[2*np],   ph[0],ph[1],ph[2],ph[3], vh[0],vh[1]);
                    mma_bf16(o[2*np],   ph[0],ph[1],ph[2],ph[3], vl[0],vl[1]);
                    mma_bf16(o[2*np],   pl[0],pl[1],pl[2],pl[3], vh[0],vh[1]);
                    mma_bf16(o[2*np+1], ph[0],ph[1],ph[2],ph[3], vh[2],vh[3]);
                    mma_bf16(o[2*np+1], ph[0],ph[1],ph[2],ph[3], vl[2],vl[3]);
                    mma_bf16(o[2*np+1], pl[0],pl[1],pl[2],pl[3], vh[2],vh[3]);
                }
            }
        }

        __syncthreads();
        if (it + 2 < niter) load_kv((it + 2) << 5, it & 1);
        asm volatile("cp.async.commit_group;" ::: "memory");
    }

    const float i0 = 1.0f / lr0, i1 = 1.0f / lr1;
    const size_t r0g = (size_t)(b * Tt + q0 + rw + (lane >> 2)) * Ccn
                     + h * Dd + ((lane & 3) << 1);
    const size_t r1g = r0g + 8 * (size_t)Ccn;
#pragma unroll
    for (int nt = 0; nt < 16; nt++) {
        uint32_t hi, lo;
        split2(o[nt][0] * i0, o[nt][1] * i0, hi, lo);
        *(uint32_t*)(Yh_g + r0g + (nt << 3)) = hi;
        *(uint32_t*)(Yl_g + r0g + (nt << 3)) = lo;
        split2(o[nt][2] * i1, o[nt][3] * i1, hi, lo);
        *(uint32_t*)(Yh_g + r1g + (nt << 3)) = hi;
        *(uint32_t*)(Yl_g + r1g + (nt << 3)) = lo;
    }
}

// ---------------------------------------------------------------------------
extern "C" void kernel_launch(void* const* d_in, const int* in_sizes, int n_in,
                              void* d_out, int out_size)
{
    (void)in_sizes; (void)n_in; (void)out_size;
    const float* x  = (const float*)d_in[0];
    const float* wq = (const float*)d_in[1];
    const float* wk = (const float*)d_in[2];
    const float* wv = (const float*)d_in[3];
    const float* wo = (const float*)d_in[4];
    float* out = (float*)d_out;

    __nv_bfloat16 *xhi, *xlo, *whi, *wlo;
    __nv_bfloat16 *qh, *ql, *kh, *kl, *vh, *vl, *yh, *yl;
    cudaGetSymbolAddress((void**)&xhi, g_xhi);
    cudaGetSymbolAddress((void**)&xlo, g_xlo);
    cudaGetSymbolAddress((void**)&whi, g_whi);
    cudaGetSymbolAddress((void**)&wlo, g_wlo);
    cudaGetSymbolAddress((void**)&qh, g_qh);
    cudaGetSymbolAddress((void**)&ql, g_ql);
    cudaGetSymbolAddress((void**)&kh, g_kh);
    cudaGetSymbolAddress((void**)&kl, g_kl);
    cudaGetSymbolAddress((void**)&vh, g_vh);
    cudaGetSymbolAddress((void**)&vl, g_vl);
    cudaGetSymbolAddress((void**)&yh, g_yh);
    cudaGetSymbolAddress((void**)&yl, g_yl);

    cudaFuncSetAttribute(gemm3_mma,
                         cudaFuncAttributeMaxDynamicSharedMemorySize, GEMM_SMEM);
    cudaFuncSetAttribute(flash_mma,
                         cudaFuncAttributeMaxDynamicSharedMemorySize, FLASH_SMEM);

    const size_t WN = (size_t)Ccn * Ccn;
    const int n4x = Mrows * Ccn / 4;
    const int n4w = (int)(WN / 4);

    split_bf16<<<n4x / 256, 256>>>(x, xhi, xlo, n4x, 1);
    split_w4<<<dim3(n4w / 256, 4), 256>>>(wq, wk, wv, wo, whi, wlo, n4w);

    // fused QKV projection + rotary + bf16 split (R8 geometry)
    dim3 gqkv(Ccn / 128, Mrows / 128, 3);
    gemm3_mma<<<gqkv, 256, GEMM_SMEM>>>(xhi, xlo, whi, wlo,
                                        nullptr, qh, ql, kh, kl, vh, vl,
                                        Mrows, Ccn, Ccn, 0);

    // flash attention: BM=64/BN=32, 128 threads, 2 CTAs/SM (R8 version)
    flash_mma<<<dim3(Tt / 64, Hh, Bb), 128, FLASH_SMEM>>>(qh, ql, kh, kl, vh, vl, yh, yl);

    // output projection (fp32 out)
    dim3 go(Ccn / 128, Mrows / 128, 1);
    gemm3_mma<<<go, 256, GEMM_SMEM>>>(yh, yl, whi + 3 * WN, wlo + 3 * WN,
                                      out, nullptr, nullptr, nullptr, nullptr,
                                      nullptr, nullptr,
                                      Mrows, Ccn, Ccn, 1);
}

// round 16
// speedup vs baseline: 1.0336x; 1.0084x over previous
#include <cuda_runtime.h>
#include <cuda_bf16.h>
#include <math.h>
#include <stdint.h>

#define Bb 4
#define Tt 2048
#define Ccn 2048
#define Hh 16
#define Dd 128
#define Mrows (Bb*Tt)   // 8192

// ---------------- scratch (device globals) ----------------
__device__ float g_invfreq[Dd/2];

__device__ __align__(256) __nv_bfloat16 g_xhi[Mrows*Ccn];
__device__ __align__(256) __nv_bfloat16 g_xlo[Mrows*Ccn];
__device__ __align__(256) __nv_bfloat16 g_qh[Mrows*Ccn];
__device__ __align__(256) __nv_bfloat16 g_ql[Mrows*Ccn];
__device__ __align__(256) __nv_bfloat16 g_kh[Mrows*Ccn];
__device__ __align__(256) __nv_bfloat16 g_kl[Mrows*Ccn];
__device__ __align__(256) __nv_bfloat16 g_vh[Mrows*Ccn];
__device__ __align__(256) __nv_bfloat16 g_vl[Mrows*Ccn];
__device__ __align__(256) __nv_bfloat16 g_yh[Mrows*Ccn];
__device__ __align__(256) __nv_bfloat16 g_yl[Mrows*Ccn];
__device__ __align__(256) __nv_bfloat16 g_whi[4][Ccn*Ccn];
__device__ __align__(256) __nv_bfloat16 g_wlo[4][Ccn*Ccn];

// ---------------- helpers ----------------
__device__ __forceinline__ uint32_t smem_u32(const void* p) {
    uint32_t a;
    asm("{ .reg .u64 t; cvta.to.shared.u64 t, %1; cvt.u32.u64 %0, t; }"
        : "=r"(a) : "l"(p));
    return a;
}

__device__ __forceinline__ void cp16(uint32_t dst, const void* src) {
    asm volatile("cp.async.cg.shared.global [%0], [%1], 16;"
                 :: "r"(dst), "l"(src));
}

__device__ __forceinline__ void ldsm_x4(uint32_t addr, uint32_t& r0, uint32_t& r1,
                                        uint32_t& r2, uint32_t& r3) {
    asm volatile("ldmatrix.sync.aligned.m8n8.x4.shared.b16 {%0,%1,%2,%3}, [%4];"
                 : "=r"(r0), "=r"(r1), "=r"(r2), "=r"(r3) : "r"(addr));
}

__device__ __forceinline__ void ldsm_x4t(uint32_t addr, uint32_t& r0, uint32_t& r1,
                                         uint32_t& r2, uint32_t& r3) {
    asm volatile("ldmatrix.sync.aligned.m8n8.x4.trans.shared.b16 {%0,%1,%2,%3}, [%4];"
                 : "=r"(r0), "=r"(r1), "=r"(r2), "=r"(r3) : "r"(addr));
}

__device__ __forceinline__ void mma_bf16(float* d, uint32_t a0, uint32_t a1,
                                         uint32_t a2, uint32_t a3,
                                         uint32_t b0, uint32_t b1) {
    asm volatile(
        "mma.sync.aligned.m16n8k16.row.col.f32.bf16.bf16.f32 "
        "{%0,%1,%2,%3}, {%4,%5,%6,%7}, {%8,%9}, {%0,%1,%2,%3};"
        : "+f"(d[0]), "+f"(d[1]), "+f"(d[2]), "+f"(d[3])
        : "r"(a0), "r"(a1), "r"(a2), "r"(a3), "r"(b0), "r"(b1));
}

__device__ __forceinline__ void split2(float x, float y, uint32_t& hi, uint32_t& lo) {
    __nv_bfloat16 hx = __float2bfloat16(x), hy = __float2bfloat16(y);
    __nv_bfloat16 lx = __float2bfloat16(x - __bfloat162float(hx));
    __nv_bfloat16 ly = __float2bfloat16(y - __bfloat162float(hy));
    __nv_bfloat162 H = __halves2bfloat162(hx, hy);
    __nv_bfloat162 L = __halves2bfloat162(lx, ly);
    hi = *(uint32_t*)&H;
    lo = *(uint32_t*)&L;
}

// ---------------------------------------------------------------------------
// bf16 split for x (+ invfreq init in block 0)
// ---------------------------------------------------------------------------
__global__ void split_bf16(const float* __restrict__ X,
                           __nv_bfloat16* __restrict__ H,
                           __nv_bfloat16* __restrict__ L, int n4, int do_init)
{
    if (do_init && blockIdx.x == 0 && threadIdx.x < Dd / 2)
        g_invfreq[threadIdx.x] =
            (float)exp(-((double)(2 * threadIdx.x) / (double)Dd) * log(10000.0));

    int i = blockIdx.x * blockDim.x + threadIdx.x;
    if (i >= n4) return;
    float4 v = ((const float4*)X)[i];
    __nv_bfloat16 h0 = __float2bfloat16(v.x);
    __nv_bfloat16 h1 = __float2bfloat16(v.y);
    __nv_bfloat16 h2 = __float2bfloat16(v.z);
    __nv_bfloat16 h3 = __float2bfloat16(v.w);
    __nv_bfloat16 l0 = __float2bfloat16(v.x - __bfloat162float(h0));
    __nv_bfloat16 l1 = __float2bfloat16(v.y - __bfloat162float(h1));
    __nv_bfloat16 l2 = __float2bfloat16(v.z - __bfloat162float(h2));
    __nv_bfloat16 l3 = __float2bfloat16(v.w - __bfloat162float(h3));
    __nv_bfloat162* Hp = (__nv_bfloat162*)H;
    __nv_bfloat162* Lp = (__nv_bfloat162*)L;
    Hp[2*i]   = __halves2bfloat162(h0, h1);
    Hp[2*i+1] = __halves2bfloat162(h2, h3);
    Lp[2*i]   = __halves2bfloat162(l0, l1);
    Lp[2*i+1] = __halves2bfloat162(l2, l3);
}

// fused split of all 4 weight matrices (one launch)
__global__ void split_w4(const float* __restrict__ W0, const float* __restrict__ W1,
                         const float* __restrict__ W2, const float* __restrict__ W3,
                         __nv_bfloat16* __restrict__ H, __nv_bfloat16* __restrict__ L,
                         int n4)
{
    int zi = blockIdx.y;
    const float* X = (zi == 0) ? W0 : (zi == 1) ? W1 : (zi == 2) ? W2 : W3;
    __nv_bfloat16* Hd = H + (size_t)zi * (size_t)Ccn * Ccn;
    __nv_bfloat16* Ld = L + (size_t)zi * (size_t)Ccn * Ccn;

    int i = blockIdx.x * blockDim.x + threadIdx.x;
    if (i >= n4) return;
    float4 v = ((const float4*)X)[i];
    __nv_bfloat16 h0 = __float2bfloat16(v.x);
    __nv_bfloat16 h1 = __float2bfloat16(v.y);
    __nv_bfloat16 h2 = __float2bfloat16(v.z);
    __nv_bfloat16 h3 = __float2bfloat16(v.w);
    __nv_bfloat16 l0 = __float2bfloat16(v.x - __bfloat162float(h0));
    __nv_bfloat16 l1 = __float2bfloat16(v.y - __bfloat162float(h1));
    __nv_bfloat16 l2 = __float2bfloat16(v.z - __bfloat162float(h2));
    __nv_bfloat16 l3 = __float2bfloat16(v.w - __bfloat162float(h3));
    __nv_bfloat162* Hp = (__nv_bfloat162*)Hd;
    __nv_bfloat162* Lp = (__nv_bfloat162*)Ld;
    Hp[2*i]   = __halves2bfloat162(h0, h1);
    Hp[2*i+1] = __halves2bfloat162(h2, h3);
    Lp[2*i]   = __halves2bfloat162(l0, l1);
    Lp[2*i+1] = __halves2bfloat162(l2, l3);
}

// ---------------------------------------------------------------------------
// mma.sync bf16 3-term GEMM (NT) — R8 configuration (verified best).
// Tile 128x128, K-chunk 32, 3-stage pipeline, 256 threads, 2 CTAs/SM.
// ---------------------------------------------------------------------------
#define STAGE_BYTES 32768
#define GEMM_SMEM   (3*STAGE_BYTES)

__global__ __launch_bounds__(256, 2)
void gemm3_mma(const __nv_bfloat16* __restrict__ Ahi,
               const __nv_bfloat16* __restrict__ Alo,
               const __nv_bfloat16* __restrict__ Bh_base,
               const __nv_bfloat16* __restrict__ Bl_base,
               float* __restrict__ C,
               __nv_bfloat16* __restrict__ QH, __nv_bfloat16* __restrict__ QL,
               __nv_bfloat16* __restrict__ KH, __nv_bfloat16* __restrict__ KL,
               __nv_bfloat16* __restrict__ VH, __nv_bfloat16* __restrict__ VL,
               int M, int N, int K, int mode)
{
    extern __shared__ char smraw[];
    const uint32_t smb = smem_u32(smraw);

    const int tid  = threadIdx.x;
    const int lane = tid & 31;
    const int w    = tid >> 5;
    const int wm   = w & 3;
    const int wn   = w >> 2;
    const int m0   = blockIdx.y << 7;
    const int n0   = blockIdx.x << 7;
    const int z    = blockIdx.z;
    const int NC   = K >> 5;

    const __nv_bfloat16* Bhi = Bh_base + (size_t)z * K * N;
    const __nv_bfloat16* Blo = Bl_base + (size_t)z * K * N;
    const __nv_bfloat16* gsrc[4] = {Ahi, Alo, Bhi, Blo};

    auto load_stage = [&](int c, int s) {
        const int kk = c << 5;
        const uint32_t st = smb + (uint32_t)s * STAGE_BYTES;
#pragma unroll
        for (int buf = 0; buf < 4; buf++) {
            const __nv_bfloat16* src = gsrc[buf];
            const int rbase = (buf < 2) ? m0 : n0;
#pragma unroll
            for (int t = 0; t < 2; t++) {
                int cidx = tid + (t << 8);
                int r = cidx >> 2;
                uint32_t cb = (uint32_t)(cidx & 3) << 4;
                uint32_t dst = st + (uint32_t)buf * 8192 + (r << 6)
                             + (cb ^ (((r >> 1) & 3) << 4));
                cp16(dst, src + (size_t)(rbase + r) * K + kk + ((cidx & 3) << 3));
            }
        }
    };

    float acc[2][8][4];
#pragma unroll
    for (int mi = 0; mi < 2; mi++)
#pragma unroll
        for (int ni = 0; ni < 8; ni++)
#pragma unroll
            for (int j = 0; j < 4; j++) acc[mi][ni][j] = 0.0f;

    load_stage(0, 0);
    asm volatile("cp.async.commit_group;" ::: "memory");
    load_stage(1, 1);
    asm volatile("cp.async.commit_group;" ::: "memory");

    const int a_row = (wm << 5) + (lane & 15);
    const uint32_t a_cb = (uint32_t)((lane >> 4) << 4);
    const int b_row = (wn << 6) + (lane & 7) + ((lane >> 4) << 3);
    const uint32_t b_cb = (uint32_t)(((lane >> 3) & 1) << 4);

    for (int c = 0; c < NC; c++) {
        asm volatile("cp.async.wait_group 1;" ::: "memory");
        __syncthreads();
        if (c + 2 < NC) load_stage(c + 2, (c + 2) % 3);
        asm volatile("cp.async.commit_group;" ::: "memory");

        const uint32_t st = smb + (uint32_t)(c % 3) * STAGE_BYTES;
        const uint32_t sAhi = st,           sAlo = st + 8192;
        const uint32_t sBhi = st + 16384,   sBlo = st + 24576;

#pragma unroll
        for (int kq = 0; kq < 2; kq++) {
            const uint32_t kb = (uint32_t)kq << 5;

            uint32_t ah[2][4], al[2][4];
#pragma unroll
            for (int mi = 0; mi < 2; mi++) {
                int row = a_row + (mi << 4);
                uint32_t off = (uint32_t)(row << 6)
                             + ((kb + a_cb) ^ (((row >> 1) & 3) << 4));
                ldsm_x4(sAhi + off, ah[mi][0], ah[mi][1], ah[mi][2], ah[mi][3]);
                ldsm_x4(sAlo + off, al[mi][0], al[mi][1], al[mi][2], al[mi][3]);
            }

#pragma unroll
            for (int np = 0; np < 4; np++) {
                int row = b_row + (np << 4);
                uint32_t off = (uint32_t)(row << 6)
                             + ((kb + b_cb) ^ (((row >> 1) & 3) << 4));
                uint32_t kh[4], kl[4];
                ldsm_x4(sBhi + off, kh[0], kh[1], kh[2], kh[3]);
                ldsm_x4(sBlo + off, kl[0], kl[1], kl[2], kl[3]);
#pragma unroll
                for (int mi = 0; mi < 2; mi++) {
                    mma_bf16(acc[mi][2*np],   ah[mi][0],ah[mi][1],ah[mi][2],ah[mi][3], kh[0],kh[1]);
                    mma_bf16(acc[mi][2*np],   ah[mi][0],ah[mi][1],ah[mi][2],ah[mi][3], kl[0],kl[1]);
                    mma_bf16(acc[mi][2*np],   al[mi][0],al[mi][1],al[mi][2],al[mi][3], kh[0],kh[1]);
                    mma_bf16(acc[mi][2*np+1], ah[mi][0],ah[mi][1],ah[mi][2],ah[mi][3], kh[2],kh[3]);
                    mma_bf16(acc[mi][2*np+1], ah[mi][0],ah[mi][1],ah[mi][2],ah[mi][3], kl[2],kl[3]);
                    mma_bf16(acc[mi][2*np+1], al[mi][0],al[mi][1],al[mi][2],al[mi][3], kh[2],kh[3]);
                }
            }
        }
    }

    // ---- epilogue ----
    if (mode == 1) {
#pragma unroll
        for (int mi = 0; mi < 2; mi++) {
            int r0g = m0 + (wm << 5) + (mi << 4) + (lane >> 2);
#pragma unroll
            for (int ni = 0; ni < 8; ni++) {
                int col = n0 + (wn << 6) + (ni << 3) + ((lane & 3) << 1);
                *(float2*)(C + (size_t)r0g * N + col) =
                    make_float2(acc[mi][ni][0], acc[mi][ni][1]);
                *(float2*)(C + (size_t)(r0g + 8) * N + col) =
                    make_float2(acc[mi][ni][2], acc[mi][ni][3]);
            }
        }
        return;
    }

    if (z == 2) {   // V: direct bf16 hi/lo split
#pragma unroll
        for (int mi = 0; mi < 2; mi++) {
            int r0g = m0 + (wm << 5) + (mi << 4) + (lane >> 2);
#pragma unroll
            for (int ni = 0; ni < 8; ni++) {
                int col = n0 + (wn << 6) + (ni << 3) + ((lane & 3) << 1);
                uint32_t hi, lo;
                split2(acc[mi][ni][0], acc[mi][ni][1], hi, lo);
                *(uint32_t*)(VH + (size_t)r0g * N + col) = hi;
                *(uint32_t*)(VL + (size_t)r0g * N + col) = lo;
                split2(acc[mi][ni][2], acc[mi][ni][3], hi, lo);
                *(uint32_t*)(VH + (size_t)(r0g + 8) * N + col) = hi;
                *(uint32_t*)(VL + (size_t)(r0g + 8) * N + col) = lo;
            }
        }
        return;
    }

    // z = 0 (Q) or 1 (K): double rotary fused via smem exchange.
    __syncthreads();
    float* sred = (float*)smraw;           // 128 x 132 fp32
#pragma unroll
    for (int mi = 0; mi < 2; mi++) {
        int r0 = (wm << 5) + (mi << 4) + (lane >> 2);
#pragma unroll
        for (int ni = 0; ni < 8; ni++) {
            int col = (wn << 6) + (ni << 3) + ((lane & 3) << 1);
            sred[r0 * 132 + col]       = acc[mi][ni][0];
            sred[r0 * 132 + col + 1]   = acc[mi][ni][1];
            sred[(r0+8) * 132 + col]   = acc[mi][ni][2];
            sred[(r0+8) * 132 + col+1] = acc[mi][ni][3];
        }
    }
    __syncthreads();

    __nv_bfloat16* H = (z == 0) ? QH : KH;
    __nv_bfloat16* L = (z == 0) ? QL : KL;
#pragma unroll 4
    for (int i = tid; i < 128 * 64; i += 256) {
        int r = i >> 6, j = i & 63;
        int m = m0 + r;
        int tpos = m & (Tt - 1);
        float f = (float)tpos * g_invfreq[j];
        float s, c;
        sincosf(f, &s, &c);
        float x1 = sred[r * 132 + j], x2 = sred[r * 132 + j + 64];
        float y1 = x1 * c + x2 * s;
        float y2 = -x1 * s + x2 * c;
        float z1 = y1 * c + y2 * s;
        float z2 = -y1 * s + y2 * c;
        __nv_bfloat16 h1 = __float2bfloat16(z1);
        __nv_bfloat16 h2 = __float2bfloat16(z2);
        size_t base = (size_t)m * N + n0 + j;
        H[base]      = h1;
        L[base]      = __float2bfloat16(z1 - __bfloat162float(h1));
        H[base + 64] = h2;
        L[base + 64] = __float2bfloat16(z2 - __bfloat162float(h2));
    }
}

// ---------------------------------------------------------------------------
// Flash attention — R8 version (verified best).
// BM=64, BN=32, D=128, 128 threads, 96KB smem => 2 CTAs/SM. Heavy tiles first.
// ---------------------------------------------------------------------------
#define FLASH_SMEM 98304

__global__ __launch_bounds__(128, 2)
void flash_mma(const __nv_bfloat16* __restrict__ Qh_g, const __nv_bfloat16* __restrict__ Ql_g,
               const __nv_bfloat16* __restrict__ Kh_g, const __nv_bfloat16* __restrict__ Kl_g,
               const __nv_bfloat16* __restrict__ Vh_g, const __nv_bfloat16* __restrict__ Vl_g,
               __nv_bfloat16* __restrict__ Yh_g, __nv_bfloat16* __restrict__ Yl_g)
{
    extern __shared__ char sm[];
    const uint32_t smb = smem_u32(sm);
    const uint32_t sQh = smb, sQl = smb + 16384;

    const int tid = threadIdx.x, lane = tid & 31, w = tid >> 5;
    const int q0 = (int)(gridDim.x - 1 - blockIdx.x) << 6;   // heavy first
    const int h = blockIdx.y, b = blockIdx.z;
    const int rw = w << 4;             // 4 warps x 16 rows

    const size_t qoff = ((size_t)(b * Tt + q0)) * Ccn + h * Dd;
    const char* Qhp = (const char*)(Qh_g + qoff);
    const char* Qlp = (const char*)(Ql_g + qoff);

    // Q tile: 64 rows x 256B per component
#pragma unroll
    for (int t = 0; t < 8; t++) {
        int c = tid + (t << 7);
        int r = c >> 4, cb = (c & 15) << 4;
        uint32_t off = (uint32_t)(r << 8) + (uint32_t)(cb ^ ((r & 7) << 4));
        size_t g = (size_t)r * (Ccn * 2) + cb;
        cp16(sQh + off, Qhp + g);
        cp16(sQl + off, Qlp + g);
    }

    const size_t kbase = ((size_t)(b * Tt)) * Ccn + h * Dd;

    auto load_kv = [&](int j0, int s) {
        uint32_t st = smb + 32768 + (uint32_t)s * 32768;
        const char* Khp = (const char*)(Kh_g + kbase + (size_t)j0 * Ccn);
        const char* Klp = (const char*)(Kl_g + kbase + (size_t)j0 * Ccn);
        const char* Vhp = (const char*)(Vh_g + kbase + (size_t)j0 * Ccn);
        const char* Vlp = (const char*)(Vl_g + kbase + (size_t)j0 * Ccn);
#pragma unroll
        for (int t = 0; t < 4; t++) {
            int c = tid + (t << 7);
            int r = c >> 4, cb = (c & 15) << 4;
            uint32_t off = (uint32_t)(r << 8) + (uint32_t)(cb ^ ((r & 7) << 4));
            size_t g = (size_t)r * (Ccn * 2) + cb;
            cp16(st + off,          Khp + g);
            cp16(st + 8192 + off,   Klp + g);
            cp16(st + 16384 + off,  Vhp + g);
            cp16(st + 24576 + off,  Vlp + g);
        }
    };

    const int niter = (q0 >> 5) + 2;
    load_kv(0, 0);
    asm volatile("cp.async.commit_group;" ::: "memory");
    load_kv(32, 1);
    asm volatile("cp.async.commit_group;" ::: "memory");

    float o[16][4];
#pragma unroll
    for (int nt = 0; nt < 16; nt++)
#pragma unroll
        for (int e = 0; e < 4; e++) o[nt][e] = 0.0f;
    float mr0 = -INFINITY, mr1 = -INFINITY, lr0 = 0.0f, lr1 = 0.0f;

    const float SC2 = 0.08838834764831843f * 1.4426950408889634f;

    for (int it = 0; it < niter; it++) {
        const int j0 = it << 5;
        const uint32_t st = smb + 32768 + (uint32_t)(it & 1) * 32768;

        if (it + 1 < niter) asm volatile("cp.async.wait_group 1;" ::: "memory");
        else                asm volatile("cp.async.wait_group 0;" ::: "memory");
        __syncthreads();

        const bool active = (q0 + rw + 15) >= j0;
        if (active) {
            float sa[4][4];
#pragma unroll
            for (int nt = 0; nt < 4; nt++)
#pragma unroll
                for (int e = 0; e < 4; e++) sa[nt][e] = 0.0f;

            const uint32_t sKh = st, sKl = st + 8192;
#pragma unroll
            for (int ks = 0; ks < 8; ks++) {
                int ar = rw + (lane & 15);
                uint32_t ao = (uint32_t)(ar << 8)
                    + (uint32_t)((((ks << 5) + ((lane >> 4) << 4))) ^ ((ar & 7) << 4));
                uint32_t qh[4], ql[4];
                ldsm_x4(sQh + ao, qh[0], qh[1], qh[2], qh[3]);
                ldsm_x4(sQl + ao, ql[0], ql[1], ql[2], ql[3]);
#pragma unroll
                for (int np = 0; np < 2; np++) {
                    int br = (np << 4) + ((lane >> 4) << 3) + (lane & 7);
                    uint32_t bo = (uint32_t)(br << 8)
                        + (uint32_t)((((ks << 5) + (((lane >> 3) & 1) << 4))) ^ ((br & 7) << 4));
                    uint32_t kh[4], kl[4];
                    ldsm_x4(sKh + bo, kh[0], kh[1], kh[2], kh[3]);
                    ldsm_x4(sKl + bo, kl[0], kl[1], kl[2], kl[3]);
                    mma_bf16(sa[2*np],   qh[0],qh[1],qh[2],qh[3], kh[0],kh[1]);
                    mma_bf16(sa[2*np],   qh[0],qh[1],qh[2],qh[3], kl[0],kl[1]);
                    mma_bf16(sa[2*np],   ql[0],ql[1],ql[2],ql[3], kh[0],kh[1]);
                    mma_bf16(sa[2*np+1], qh[0],qh[1],qh[2],qh[3], kh[2],kh[3]);
                    mma_bf16(sa[2*np+1], qh[0],qh[1],qh[2],qh[3], kl[2],kl[3]);
                    mma_bf16(sa[2*np+1], ql[0],ql[1],ql[2],ql[3], kh[2],kh[3]);
                }
            }

            const int r0p = q0 + rw + (lane >> 2);
            const int r1p = r0p + 8;
            if (j0 + 31 > q0 + rw) {
#pragma unroll
                for (int nt = 0; nt < 4; nt++) {
                    int c0 = j0 + (nt << 3) + ((lane & 3) << 1);
                    sa[nt][0] = (c0     <= r0p) ? sa[nt][0] * SC2 : -INFINITY;
                    sa[nt][1] = (c0 + 1 <= r0p) ? sa[nt][1] * SC2 : -INFINITY;
                    sa[nt][2] = (c0     <= r1p) ? sa[nt][2] * SC2 : -INFINITY;
                    sa[nt][3] = (c0 + 1 <= r1p) ? sa[nt][3] * SC2 : -INFINITY;
                }
            } else {
#pragma unroll
                for (int nt = 0; nt < 4; nt++)
#pragma unroll
                    for (int e = 0; e < 4; e++) sa[nt][e] *= SC2;
            }

            float mx0 = -INFINITY, mx1 = -INFINITY;
#pragma unroll
            for (int nt = 0; nt < 4; nt++) {
                mx0 = fmaxf(mx0, fmaxf(sa[nt][0], sa[nt][1]));
                mx1 = fmaxf(mx1, fmaxf(sa[nt][2], sa[nt][3]));
            }
            mx0 = fmaxf(mx0, __shfl_xor_sync(0xffffffffu, mx0, 1));
            mx0 = fmaxf(mx0, __shfl_xor_sync(0xffffffffu, mx0, 2));
            mx1 = fmaxf(mx1, __shfl_xor_sync(0xffffffffu, mx1, 1));
            mx1 = fmaxf(mx1, __shfl_xor_sync(0xffffffffu, mx1, 2));

            float mn0 = fmaxf(mr0, mx0), mn1 = fmaxf(mr1, mx1);
            float a0 = exp2f(mr0 - mn0), a1 = exp2f(mr1 - mn1);
            mr0 = mn0; mr1 = mn1;

            float s0 = 0.0f, s1 = 0.0f;
#pragma unroll
            for (int nt = 0; nt < 4; nt++) {
                sa[nt][0] = exp2f(sa[nt][0] - mn0);
                sa[nt][1] = exp2f(sa[nt][1] - mn0);
                sa[nt][2] = exp2f(sa[nt][2] - mn1);
                sa[nt][3] = exp2f(sa[nt][3] - mn1);
                s0 += sa[nt][0] + sa[nt][1];
                s1 += sa[nt][2] + sa[nt][3];
            }
            s0 += __shfl_xor_sync(0xffffffffu, s0, 1);
            s0 += __shfl_xor_sync(0xffffffffu, s0, 2);
            s1 += __shfl_xor_sync(0xffffffffu, s1, 1);
            s1 += __shfl_xor_sync(0xffffffffu, s1, 2);
            lr0 = lr0 * a0 + s0;
            lr1 = lr1 * a1 + s1;

#pragma unroll
            for (int nt = 0; nt < 16; nt++) {
                o[nt][0] *= a0; o[nt][1] *= a0;
                o[nt][2] *= a1; o[nt][3] *= a1;
            }

            // P @ V : P 16x32, V 32x128
            const uint32_t sVh = st + 16384, sVl = st + 24576;
#pragma unroll
            for (int kc = 0; kc < 2; kc++) {
                uint32_t ph[4], pl[4];
                split2(sa[2*kc][0],   sa[2*kc][1],   ph[0], pl[0]);
                split2(sa[2*kc][2],   sa[2*kc][3],   ph[1], pl[1]);
                split2(sa[2*kc+1][0], sa[2*kc+1][1], ph[2], pl[2]);
                split2(sa[2*kc+1][2], sa[2*kc+1][3], ph[3], pl[3]);

                int vr = (kc << 4) + (((lane >> 3) & 1) << 3) + (lane & 7);
#pragma unroll
                for (int np = 0; np < 8; np++) {
                    uint32_t vo = (uint32_t)(vr << 8)
                        + (uint32_t)((((np << 5) + ((lane >> 4) << 4))) ^ ((vr & 7) << 4));
                    uint32_t vh[4], vl[4];
                    ldsm_x4t(sVh + vo, vh[0], vh[1], vh[2], vh[3]);
                    ldsm_x4t(sVl + vo, vl[0], vl[1], vl[2], vl[3]);
                    mma_bf16(o[2*np],   ph[0],ph[1],ph[2],ph[3], vh[0],vh[1]);
                    mma_bf16(o[2*np],   ph[0],ph[1],ph[2],ph[3], vl[0],vl[1]);
                    mma_bf16(o[2*np],   pl[0],pl[1],pl[2],pl[3], vh[0],vh[1]);
                    mma_bf16(o[2*np+1], ph[0],ph[1],ph[2],ph[3], vh[2],vh[3]);
                    mma_bf16(o[2*np+1], ph[0],ph[1],ph[2],ph[3], vl[2],vl[3]);
                    mma_bf16(o[2*np+1], pl[0],pl[1],pl[2],pl[3], vh[2],vh[3]);
                }
            }
        }

        __syncthreads();
        if (it + 2 < niter) load_kv((it + 2) << 5, it & 1);
        asm volatile("cp.async.commit_group;" ::: "memory");
    }

    const float i0 = 1.0f / lr0, i1 = 1.0f / lr1;
    const size_t r0g = (size_t)(b * Tt + q0 + rw + (lane >> 2)) * Ccn
                     + h * Dd + ((lane & 3) << 1);
    const size_t r1g = r0g + 8 * (size_t)Ccn;
#pragma unroll
    for (int nt = 0; nt < 16; nt++) {
        uint32_t hi, lo;
        split2(o[nt][0] * i0, o[nt][1] * i0, hi, lo);
        *(uint32_t*)(Yh_g + r0g + (nt << 3)) = hi;
        *(uint32_t*)(Yl_g + r0g + (nt << 3)) = lo;
        split2(o[nt][2] * i1, o[nt][3] * i1, hi, lo);
        *(uint32_t*)(Yh_g + r1g + (nt << 3)) = hi;
        *(uint32_t*)(Yl_g + r1g + (nt << 3)) = lo;
    }
}

// ---------------------------------------------------------------------------
extern "C" void kernel_launch(void* const* d_in, const int* in_sizes, int n_in,
                              void* d_out, int out_size)
{
    (void)in_sizes; (void)n_in; (void)out_size;
    const float* x  = (const float*)d_in[0];
    const float* wq = (const float*)d_in[1];
    const float* wk = (const float*)d_in[2];
    const float* wv = (const float*)d_in[3];
    const float* wo = (const float*)d_in[4];
    float* out = (float*)d_out;

    __nv_bfloat16 *xhi, *xlo, *whi, *wlo;
    __nv_bfloat16 *qh, *ql, *kh, *kl, *vh, *vl, *yh, *yl;
    cudaGetSymbolAddress((void**)&xhi, g_xhi);
    cudaGetSymbolAddress((void**)&xlo, g_xlo);
    cudaGetSymbolAddress((void**)&whi, g_whi);
    cudaGetSymbolAddress((void**)&wlo, g_wlo);
    cudaGetSymbolAddress((void**)&qh, g_qh);
    cudaGetSymbolAddress((void**)&ql, g_ql);
    cudaGetSymbolAddress((void**)&kh, g_kh);
    cudaGetSymbolAddress((void**)&kl, g_kl);
    cudaGetSymbolAddress((void**)&vh, g_vh);
    cudaGetSymbolAddress((void**)&vl, g_vl);
    cudaGetSymbolAddress((void**)&yh, g_yh);
    cudaGetSymbolAddress((void**)&yl, g_yl);

    cudaFuncSetAttribute(gemm3_mma,
                         cudaFuncAttributeMaxDynamicSharedMemorySize, GEMM_SMEM);
    cudaFuncSetAttribute(flash_mma,
                         cudaFuncAttributeMaxDynamicSharedMemorySize, FLASH_SMEM);

    const size_t WN = (size_t)Ccn * Ccn;
    const int n4x = Mrows * Ccn / 4;
    const int n4w = (int)(WN / 4);

    split_bf16<<<n4x / 256, 256>>>(x, xhi, xlo, n4x, 1);
    split_w4<<<dim3(n4w / 256, 4), 256>>>(wq, wk, wv, wo, whi, wlo, n4w);

    // fused QKV projection + rotary + bf16 split
    dim3 gqkv(Ccn / 128, Mrows / 128, 3);
    gemm3_mma<<<gqkv, 256, GEMM_SMEM>>>(xhi, xlo, whi, wlo,
                                        nullptr, qh, ql, kh, kl, vh, vl,
                                        Mrows, Ccn, Ccn, 0);

    // flash attention: BM=64/BN=32, 128 threads, 2 CTAs/SM
    flash_mma<<<dim3(Tt / 64, Hh, Bb), 128, FLASH_SMEM>>>(qh, ql, kh, kl, vh, vl, yh, yl);

    // output projection (fp32 out)
    dim3 go(Ccn / 128, Mrows / 128, 1);
    gemm3_mma<<<go, 256, GEMM_SMEM>>>(yh, yl, whi + 3 * WN, wlo + 3 * WN,
                                      out, nullptr, nullptr, nullptr, nullptr,
                                      nullptr, nullptr,
                                      Mrows, Ccn, Ccn, 1);
}